// round 2
// baseline (speedup 1.0000x reference)
#include <cuda_runtime.h>
#include <cuda_bf16.h>
#include <cstdint>

// Problem constants
#define BB    4
#define CC    19
#define HWN   (512 * 1024)          // 524288 pixels per batch
#define NPIX  (BB * HWN)            // 2097152
#define NPIX4 (NPIX / 4)            // 524288
#define HW4   (HWN / 4)             // 131072 float4 per channel-plane
#define TOPK  1468006u              // int(0.7 * 2097152)
#define NBINS 4096
#define NSLOT1 8                    // contention-spreading slots, coarse merge
#define NSLOT2 4                    // slots, fine merge

// Scratch (static device arrays — allowed)
__device__ float4       g_loss4[NPIX4];              // 8 MB pixel losses
__device__ unsigned int g_hist1[NSLOT1][NBINS];      // coarse counts (bits >> 20)
__device__ double       g_bsum1[NSLOT1][NBINS];      // coarse per-bin value sums
__device__ unsigned int g_hist2[NSLOT2][NBINS];      // fine counts ((bits>>8)&0xFFF) in b*
__device__ double       g_bsum2[NSLOT2][NBINS];      // fine per-bin value sums in b*
__device__ double       g_sum_gt;                    // sum of values in coarse bins > b*
__device__ unsigned int g_bstar;                     // coarse threshold bin
__device__ unsigned int g_need;                      // elements still needed from bin b*

// ---------------------------------------------------------------------------
// K0: zero coarse scratch (fine scratch is zeroed inside select pass 0)
// ---------------------------------------------------------------------------
__global__ void zero_kernel() {
    int t = blockIdx.x * blockDim.x + threadIdx.x;
    int n = gridDim.x * blockDim.x;
    for (int i = t; i < NSLOT1 * NBINS; i += n) {
        ((unsigned*)g_hist1)[i] = 0u;
        ((double*)g_bsum1)[i]   = 0.0;
    }
    if (t == 0) g_sum_gt = 0.0;
}

// ---------------------------------------------------------------------------
// K1: fused loss compute + coarse histogram + coarse per-bin sums
// loss_p = (sum_c s*w) * log(sum_c exp(l)) - sum_c s*w*l   (no max-sub; |l|<~6)
// ---------------------------------------------------------------------------
__global__ void __launch_bounds__(256) loss_kernel(const float4* __restrict__ logits,
                                                   const float4* __restrict__ smooth,
                                                   const float*  __restrict__ w2) {
    __shared__ float    s_w[32];
    __shared__ unsigned s_h[NBINS];
    __shared__ float    s_s[NBINS];

    int t = threadIdx.x;
    if (t < CC) s_w[t] = w2[t];
    for (int i = t; i < NBINS; i += 256) { s_h[i] = 0u; s_s[i] = 0.f; }
    __syncthreads();

    int tid = blockIdx.x * 256 + t;        // 0 .. NPIX4-1 (grid sized exactly)
    int p   = tid << 2;                    // pixel base index
    int b   = p >> 19;                     // batch  (p / HWN)
    int hw  = p & (HWN - 1);
    int base4 = b * (CC * HW4) + (hw >> 2);

    const float4* Lp = logits + base4;
    const float4* Sp = smooth + base4;

    float eX = 0.f, eY = 0.f, eZ = 0.f, eW = 0.f;        // sum exp
    float swX = 0.f, swY = 0.f, swZ = 0.f, swW = 0.f;    // sum s*w
    float slX = 0.f, slY = 0.f, slZ = 0.f, slW = 0.f;    // sum s*w*l

    #pragma unroll
    for (int c = 0; c < CC; c++) {
        float4 l = Lp[c * HW4];
        float4 s = Sp[c * HW4];
        float wc = s_w[c];
        eX += __expf(l.x); eY += __expf(l.y); eZ += __expf(l.z); eW += __expf(l.w);
        float a = s.x * wc, bb2 = s.y * wc, cc2 = s.z * wc, dd = s.w * wc;
        swX += a;        swY += bb2;       swZ += cc2;       swW += dd;
        slX += a * l.x;  slY += bb2 * l.y; slZ += cc2 * l.z; slW += dd * l.w;
    }

    float4 loss;
    loss.x = swX * __logf(eX) - slX;
    loss.y = swY * __logf(eY) - slY;
    loss.z = swZ * __logf(eZ) - slZ;
    loss.w = swW * __logf(eW) - slW;
    g_loss4[tid] = loss;

    {
        unsigned bx = __float_as_uint(loss.x) >> 20;
        unsigned by = __float_as_uint(loss.y) >> 20;
        unsigned bz = __float_as_uint(loss.z) >> 20;
        unsigned bw = __float_as_uint(loss.w) >> 20;
        atomicAdd(&s_h[bx], 1u); atomicAdd(&s_s[bx], loss.x);
        atomicAdd(&s_h[by], 1u); atomicAdd(&s_s[by], loss.y);
        atomicAdd(&s_h[bz], 1u); atomicAdd(&s_s[bz], loss.z);
        atomicAdd(&s_h[bw], 1u); atomicAdd(&s_s[bw], loss.w);
    }

    __syncthreads();
    int slot = blockIdx.x & (NSLOT1 - 1);
    for (int i = t; i < NBINS; i += 256) {
        unsigned c = s_h[i];
        if (c) {
            atomicAdd(&g_hist1[slot][i], c);
            atomicAdd(&g_bsum1[slot][i], (double)s_s[i]);
        }
    }
}

// ---------------------------------------------------------------------------
// K3: fine histogram + sums of elements inside coarse bin b* (pure float loop)
// ---------------------------------------------------------------------------
__global__ void __launch_bounds__(256) fine_kernel() {
    __shared__ unsigned s_h[NBINS];
    __shared__ float    s_s[NBINS];

    int t = threadIdx.x;
    for (int i = t; i < NBINS; i += 256) { s_h[i] = 0u; s_s[i] = 0.f; }
    __syncthreads();

    unsigned bstar = g_bstar;

    for (int i = blockIdx.x * 256 + t; i < NPIX4; i += gridDim.x * 256) {
        float4 v4 = g_loss4[i];
        float vv[4] = { v4.x, v4.y, v4.z, v4.w };
        #pragma unroll
        for (int j = 0; j < 4; j++) {
            unsigned bits = __float_as_uint(vv[j]);
            if ((bits >> 20) == bstar) {
                unsigned fb = (bits >> 8) & 0xFFFu;
                atomicAdd(&s_h[fb], 1u);
                atomicAdd(&s_s[fb], vv[j]);
            }
        }
    }

    __syncthreads();
    int slot = blockIdx.x & (NSLOT2 - 1);
    for (int i = t; i < NBINS; i += 256) {
        unsigned c = s_h[i];
        if (c) {
            atomicAdd(&g_hist2[slot][i], c);
            atomicAdd(&g_bsum2[slot][i], (double)s_s[i]);
        }
    }
}

// ---------------------------------------------------------------------------
// K2 / K4: top-down scan over a (slotted) 4096-bin histogram.
// pass 0: hist1, K = TOPK  -> g_bstar, g_need, g_sum_gt; zero fine scratch
// pass 1: hist2, K = g_need -> finalize result into out[0]
// ---------------------------------------------------------------------------
__global__ void __launch_bounds__(1024) select_kernel(int pass, float* out) {
    __shared__ unsigned s_cum[NBINS];
    __shared__ unsigned s_wsum[32];
    __shared__ int      s_r;
    __shared__ unsigned s_need2;
    __shared__ double   s_red[32];

    int t = threadIdx.x;
    int lane = t & 31, wid = t >> 5;
    unsigned K = (pass == 0) ? TOPK : g_need;

    // each thread: 4 reversed bins (slot-combined), serial inclusive sums
    unsigned c0, c1, c2, c3;
    {
        unsigned v[4];
        #pragma unroll
        for (int j = 0; j < 4; j++) {
            int bin = 4095 - (4 * t + j);
            unsigned acc = 0;
            if (pass == 0) {
                #pragma unroll
                for (int s = 0; s < NSLOT1; s++) acc += g_hist1[s][bin];
            } else {
                #pragma unroll
                for (int s = 0; s < NSLOT2; s++) acc += g_hist2[s][bin];
            }
            v[j] = acc;
        }
        c0 = v[0]; c1 = c0 + v[1]; c2 = c1 + v[2]; c3 = c2 + v[3];
    }
    unsigned tot = c3;

    // warp inclusive scan of per-thread totals
    unsigned x = tot;
    #pragma unroll
    for (int o = 1; o < 32; o <<= 1) {
        unsigned y = __shfl_up_sync(0xffffffffu, x, o);
        if (lane >= o) x += y;
    }
    if (lane == 31) s_wsum[wid] = x;
    __syncthreads();
    if (wid == 0) {
        unsigned wx = s_wsum[lane];
        #pragma unroll
        for (int o = 1; o < 32; o <<= 1) {
            unsigned y = __shfl_up_sync(0xffffffffu, wx, o);
            if (lane >= o) wx += y;
        }
        s_wsum[lane] = wx;
    }
    __syncthreads();
    unsigned ex = (wid ? s_wsum[wid - 1] : 0u) + (x - tot);  // exclusive prefix
    s_cum[4 * t + 0] = ex + c0;
    s_cum[4 * t + 1] = ex + c1;
    s_cum[4 * t + 2] = ex + c2;
    s_cum[4 * t + 3] = ex + c3;
    __syncthreads();

    #pragma unroll
    for (int j = 0; j < 4; j++) {
        int r = 4 * t + j;
        unsigned cum  = s_cum[r];
        unsigned prev = r ? s_cum[r - 1] : 0u;
        if (cum >= K && prev < K) { s_r = r; s_need2 = K - prev; }
    }
    __syncthreads();

    int r = s_r;
    unsigned need = s_need2;
    int bin = 4095 - r;

    if (pass == 0) {
        // sum of coarse-bin sums strictly above b*
        double acc = 0.0;
        for (int b2 = bin + 1 + t; b2 < NBINS; b2 += 1024) {
            #pragma unroll
            for (int s = 0; s < NSLOT1; s++) acc += g_bsum1[s][b2];
        }
        #pragma unroll
        for (int o = 16; o; o >>= 1) acc += __shfl_down_sync(0xffffffffu, acc, o);
        if (lane == 0) s_red[wid] = acc;
        __syncthreads();
        if (t == 0) {
            double s = 0.0;
            #pragma unroll
            for (int i = 0; i < 32; i++) s += s_red[i];
            g_sum_gt = s;
            g_bstar = (unsigned)bin;
            g_need  = need;
        }
        // zero fine scratch for fine_kernel
        for (int i = t; i < NSLOT2 * NBINS; i += 1024) {
            ((unsigned*)g_hist2)[i] = 0u;
            ((double*)g_bsum2)[i]   = 0.0;
        }
        return;
    }

    // pass 1: sum fine-bin sums strictly above the threshold fine bin
    double acc = 0.0;
    for (int b2 = bin + 1 + t; b2 < NBINS; b2 += 1024) {
        #pragma unroll
        for (int s = 0; s < NSLOT2; s++) acc += g_bsum2[s][b2];
    }
    #pragma unroll
    for (int o = 16; o; o >>= 1) acc += __shfl_down_sync(0xffffffffu, acc, o);
    if (lane == 0) s_red[wid] = acc;
    __syncthreads();
    if (t == 0) {
        double fine_above = 0.0;
        #pragma unroll
        for (int i = 0; i < 32; i++) fine_above += s_red[i];
        double tie_sum = 0.0; unsigned tie_cnt = 0;
        #pragma unroll
        for (int s = 0; s < NSLOT2; s++) { tie_sum += g_bsum2[s][bin]; tie_cnt += g_hist2[s][bin]; }
        double tie = (double)need * (tie_sum / (double)tie_cnt);
        double total = g_sum_gt + fine_above + tie;
        out[0] = (float)(total / (double)TOPK);
    }
}

// ---------------------------------------------------------------------------
extern "C" void kernel_launch(void* const* d_in, const int* in_sizes, int n_in,
                              void* d_out, int out_size) {
    const float4* logits = (const float4*)d_in[0];
    // d_in[1] = labels (int64) — unused by the reference computation
    const float4* smooth = (const float4*)d_in[2];
    const float*  w2     = (const float*)d_in[3];
    float* out = (float*)d_out;

    zero_kernel<<<64, 256>>>();
    loss_kernel<<<NPIX4 / 256, 256>>>(logits, smooth, w2);
    select_kernel<<<1, 1024>>>(0, out);
    fine_kernel<<<592, 256>>>();
    select_kernel<<<1, 1024>>>(1, out);
}

// round 3
// speedup vs baseline: 1.3984x; 1.3984x over previous
#include <cuda_runtime.h>
#include <cuda_bf16.h>
#include <cstdint>

// Problem constants
#define BB    4
#define CC    19
#define HWN   (512 * 1024)          // 524288 pixels per batch
#define NPIX  (BB * HWN)            // 2097152
#define NPIX4 (NPIX / 4)            // 524288
#define HW4   (HWN / 4)             // 131072 float4 per channel-plane
#define TOPK  1468006u              // int(0.7 * 2097152)
#define NBINS 4096
#define FINE_GRID 1184              // 148 SMs * 8

// Scratch (static device arrays — allowed)
__device__ float4       g_loss4[NPIX4];          // 8 MB pixel losses
__device__ unsigned int g_hist1[NBINS];          // coarse counts (bits >> 20)
__device__ unsigned int g_hist2[NBINS];          // fine counts ((bits>>8)&0xFFF) in b*
__device__ double       g_sum2[NBINS];           // fine per-bin value sums in b*
__device__ double       g_sum_gt;                // sum of values in coarse bins > b*
__device__ unsigned int g_bstar;                 // coarse threshold bin
__device__ unsigned int g_need;                  // elements still needed from bin b*

// ---------------------------------------------------------------------------
// K0: zero scratch
// ---------------------------------------------------------------------------
__global__ void zero_kernel() {
    int t = blockIdx.x * blockDim.x + threadIdx.x;
    int n = gridDim.x * blockDim.x;
    for (int i = t; i < NBINS; i += n) {
        g_hist1[i] = 0u;
        g_hist2[i] = 0u;
        g_sum2[i]  = 0.0;
    }
    if (t == 0) g_sum_gt = 0.0;
}

// ---------------------------------------------------------------------------
// K1: fused loss compute + coarse count histogram (R1 form — counts ONLY;
// value sums through contended shared atomics cost ~45us in R2, never again)
// loss_p = (sum_c s*w) * log(sum_c exp(l)) - sum_c s*w*l   (no max-sub; |l|<~6)
// ---------------------------------------------------------------------------
__global__ void __launch_bounds__(256) loss_kernel(const float4* __restrict__ logits,
                                                   const float4* __restrict__ smooth,
                                                   const float*  __restrict__ w2) {
    __shared__ float    s_w[32];
    __shared__ unsigned s_h[NBINS];

    int t = threadIdx.x;
    if (t < CC) s_w[t] = w2[t];
    for (int i = t; i < NBINS; i += 256) s_h[i] = 0u;
    __syncthreads();

    int tid = blockIdx.x * 256 + t;        // 0 .. NPIX4-1 (grid sized exactly)
    int p   = tid << 2;                    // pixel base index
    int b   = p >> 19;                     // batch  (p / HWN)
    int hw  = p & (HWN - 1);
    int base4 = b * (CC * HW4) + (hw >> 2);

    const float4* Lp = logits + base4;
    const float4* Sp = smooth + base4;

    float eX = 0.f, eY = 0.f, eZ = 0.f, eW = 0.f;        // sum exp
    float swX = 0.f, swY = 0.f, swZ = 0.f, swW = 0.f;    // sum s*w
    float slX = 0.f, slY = 0.f, slZ = 0.f, slW = 0.f;    // sum s*w*l

    #pragma unroll
    for (int c = 0; c < CC; c++) {
        float4 l = Lp[c * HW4];
        float4 s = Sp[c * HW4];
        float wc = s_w[c];
        eX += __expf(l.x); eY += __expf(l.y); eZ += __expf(l.z); eW += __expf(l.w);
        float a = s.x * wc, bb2 = s.y * wc, cc2 = s.z * wc, dd = s.w * wc;
        swX += a;        swY += bb2;       swZ += cc2;       swW += dd;
        slX += a * l.x;  slY += bb2 * l.y; slZ += cc2 * l.z; slW += dd * l.w;
    }

    float4 loss;
    loss.x = swX * __logf(eX) - slX;
    loss.y = swY * __logf(eY) - slY;
    loss.z = swZ * __logf(eZ) - slZ;
    loss.w = swW * __logf(eW) - slW;
    g_loss4[tid] = loss;

    atomicAdd(&s_h[__float_as_uint(loss.x) >> 20], 1u);
    atomicAdd(&s_h[__float_as_uint(loss.y) >> 20], 1u);
    atomicAdd(&s_h[__float_as_uint(loss.z) >> 20], 1u);
    atomicAdd(&s_h[__float_as_uint(loss.w) >> 20], 1u);

    __syncthreads();
    for (int i = t; i < NBINS; i += 256) {
        unsigned c = s_h[i];
        if (c) atomicAdd(&g_hist1[i], c);
    }
}

// ---------------------------------------------------------------------------
// K3: sum of values strictly above coarse bin b* (4 independent FP32
// accumulators, no FP64 in the hot loop) + fine histogram inside b*.
// ---------------------------------------------------------------------------
__global__ void __launch_bounds__(256) fine_kernel() {
    __shared__ unsigned s_h[NBINS];
    __shared__ float    s_s[NBINS];
    __shared__ double   s_red[8];

    int t = threadIdx.x;
    for (int i = t; i < NBINS; i += 256) { s_h[i] = 0u; s_s[i] = 0.f; }
    __syncthreads();

    unsigned bstar = g_bstar;
    float g0 = 0.f, g1 = 0.f, g2 = 0.f, g3 = 0.f;   // independent partials

    for (int i = blockIdx.x * 256 + t; i < NPIX4; i += FINE_GRID * 256) {
        float4 v4 = g_loss4[i];
        unsigned bx = __float_as_uint(v4.x);
        unsigned by = __float_as_uint(v4.y);
        unsigned bz = __float_as_uint(v4.z);
        unsigned bw = __float_as_uint(v4.w);

        if ((bx >> 20) > bstar) g0 += v4.x;
        else if ((bx >> 20) == bstar) { atomicAdd(&s_h[(bx >> 8) & 0xFFFu], 1u); atomicAdd(&s_s[(bx >> 8) & 0xFFFu], v4.x); }
        if ((by >> 20) > bstar) g1 += v4.y;
        else if ((by >> 20) == bstar) { atomicAdd(&s_h[(by >> 8) & 0xFFFu], 1u); atomicAdd(&s_s[(by >> 8) & 0xFFFu], v4.y); }
        if ((bz >> 20) > bstar) g2 += v4.z;
        else if ((bz >> 20) == bstar) { atomicAdd(&s_h[(bz >> 8) & 0xFFFu], 1u); atomicAdd(&s_s[(bz >> 8) & 0xFFFu], v4.z); }
        if ((bw >> 20) > bstar) g3 += v4.w;
        else if ((bw >> 20) == bstar) { atomicAdd(&s_h[(bw >> 8) & 0xFFFu], 1u); atomicAdd(&s_s[(bw >> 8) & 0xFFFu], v4.w); }
    }

    // block-reduce gt (promote to double only here)
    double gt = (double)g0 + (double)g1 + (double)g2 + (double)g3;
    #pragma unroll
    for (int o = 16; o; o >>= 1) gt += __shfl_down_sync(0xffffffffu, gt, o);
    if ((t & 31) == 0) s_red[t >> 5] = gt;
    __syncthreads();
    if (t == 0) {
        double s = 0.0;
        #pragma unroll
        for (int i = 0; i < 8; i++) s += s_red[i];
        atomicAdd(&g_sum_gt, s);
    }
    // merge fine hist (few hundred nonzero bins)
    for (int i = t; i < NBINS; i += 256) {
        unsigned c = s_h[i];
        if (c) {
            atomicAdd(&g_hist2[i], c);
            atomicAdd(&g_sum2[i], (double)s_s[i]);
        }
    }
}

// ---------------------------------------------------------------------------
// K2 / K4: top-down scan over a 4096-bin histogram to find the threshold bin.
// pass 0: hist1, K = TOPK  -> g_bstar, g_need
// pass 1: hist2, K = g_need -> finalize result into out[0]
// ---------------------------------------------------------------------------
__global__ void __launch_bounds__(1024) select_kernel(int pass, float* out) {
    __shared__ unsigned s_cum[NBINS];
    __shared__ unsigned s_wsum[32];
    __shared__ int      s_r;
    __shared__ unsigned s_need2;
    __shared__ double   s_red[32];

    const unsigned* hist = (pass == 0) ? g_hist1 : g_hist2;
    unsigned K = (pass == 0) ? TOPK : g_need;
    int t = threadIdx.x;
    int lane = t & 31, wid = t >> 5;

    // each thread: 4 reversed bins, serial inclusive sums
    unsigned c0, c1, c2, c3;
    {
        unsigned v0 = hist[4095 - (4 * t + 0)];
        unsigned v1 = hist[4095 - (4 * t + 1)];
        unsigned v2 = hist[4095 - (4 * t + 2)];
        unsigned v3 = hist[4095 - (4 * t + 3)];
        c0 = v0; c1 = c0 + v1; c2 = c1 + v2; c3 = c2 + v3;
    }
    unsigned tot = c3;

    // warp inclusive scan of per-thread totals
    unsigned x = tot;
    #pragma unroll
    for (int o = 1; o < 32; o <<= 1) {
        unsigned y = __shfl_up_sync(0xffffffffu, x, o);
        if (lane >= o) x += y;
    }
    if (lane == 31) s_wsum[wid] = x;
    __syncthreads();
    if (wid == 0) {
        unsigned wx = s_wsum[lane];
        #pragma unroll
        for (int o = 1; o < 32; o <<= 1) {
            unsigned y = __shfl_up_sync(0xffffffffu, wx, o);
            if (lane >= o) wx += y;
        }
        s_wsum[lane] = wx;
    }
    __syncthreads();
    unsigned ex = (wid ? s_wsum[wid - 1] : 0u) + (x - tot);  // exclusive prefix
    s_cum[4 * t + 0] = ex + c0;
    s_cum[4 * t + 1] = ex + c1;
    s_cum[4 * t + 2] = ex + c2;
    s_cum[4 * t + 3] = ex + c3;
    __syncthreads();

    #pragma unroll
    for (int j = 0; j < 4; j++) {
        int r = 4 * t + j;
        unsigned cum  = s_cum[r];
        unsigned prev = r ? s_cum[r - 1] : 0u;
        if (cum >= K && prev < K) { s_r = r; s_need2 = K - prev; }
    }
    __syncthreads();

    int r = s_r;
    unsigned need = s_need2;
    int bin = 4095 - r;

    if (pass == 0) {
        if (t == 0) { g_bstar = (unsigned)bin; g_need = need; }
        return;
    }

    // pass 1: sum fine-bin sums strictly above the threshold fine bin
    double acc = 0.0;
    for (int b2 = bin + 1 + t; b2 < NBINS; b2 += 1024) acc += g_sum2[b2];
    #pragma unroll
    for (int o = 16; o; o >>= 1) acc += __shfl_down_sync(0xffffffffu, acc, o);
    if (lane == 0) s_red[wid] = acc;
    __syncthreads();
    if (t == 0) {
        double fine_above = 0.0;
        #pragma unroll
        for (int i = 0; i < 32; i++) fine_above += s_red[i];
        double tie = (double)need * (g_sum2[bin] / (double)g_hist2[bin]);
        double total = g_sum_gt + fine_above + tie;
        out[0] = (float)(total / (double)TOPK);
    }
}

// ---------------------------------------------------------------------------
extern "C" void kernel_launch(void* const* d_in, const int* in_sizes, int n_in,
                              void* d_out, int out_size) {
    const float4* logits = (const float4*)d_in[0];
    // d_in[1] = labels (int64) — unused by the reference computation
    const float4* smooth = (const float4*)d_in[2];
    const float*  w2     = (const float*)d_in[3];
    float* out = (float*)d_out;

    zero_kernel<<<16, 256>>>();
    loss_kernel<<<NPIX4 / 256, 256>>>(logits, smooth, w2);
    select_kernel<<<1, 1024>>>(0, out);
    fine_kernel<<<FINE_GRID, 256>>>();
    select_kernel<<<1, 1024>>>(1, out);
}

// round 4
// speedup vs baseline: 1.5909x; 1.1376x over previous
#include <cuda_runtime.h>
#include <cuda_bf16.h>
#include <cstdint>

// Problem constants
#define BB    4
#define CC    19
#define HWN   (512 * 1024)          // 524288 pixels per batch
#define NPIX  (BB * HWN)            // 2097152
#define NPIX4 (NPIX / 4)            // 524288
#define HW4   (HWN / 4)             // 131072 float4 per channel-plane
#define TOPK  1468006u              // int(0.7 * 2097152)
#define NBINS 4096
#define FG    512                   // fine grid: 512*256 threads = NPIX4/4 each

// Scratch (static device arrays, zero-initialized at load; self-cleaned by
// final kernel each run so graph replays start from a clean state)
__device__ float4       g_loss4[NPIX4];          // 8 MB pixel losses
__device__ unsigned int g_hist1[NBINS];          // coarse counts (bits >> 20)
__device__ unsigned int g_hist2[NBINS];          // fine counts ((bits>>8)&0xFFF) in b*
__device__ double       g_sum_gt;                // sum of values in coarse bins > b*

// ---------------------------------------------------------------------------
// K1: fused loss compute + coarse count histogram.
// loss_p = (sum_c s*w) * log(sum_c exp(l)) - sum_c s*w*l   (no max-sub; |l|<~6)
// Streaming inputs use __ldcs so the 8MB loss array stays L2-resident.
// ---------------------------------------------------------------------------
__global__ void __launch_bounds__(256) loss_kernel(const float4* __restrict__ logits,
                                                   const float4* __restrict__ smooth,
                                                   const float*  __restrict__ w2) {
    __shared__ float    s_w[32];
    __shared__ unsigned s_h[NBINS];

    int t = threadIdx.x;
    if (t < CC) s_w[t] = w2[t];
    for (int i = t; i < NBINS; i += 256) s_h[i] = 0u;
    __syncthreads();

    int tid = blockIdx.x * 256 + t;        // 0 .. NPIX4-1 (grid sized exactly)
    int p   = tid << 2;                    // pixel base index
    int b   = p >> 19;                     // batch  (p / HWN)
    int hw  = p & (HWN - 1);
    int base4 = b * (CC * HW4) + (hw >> 2);

    const float4* Lp = logits + base4;
    const float4* Sp = smooth + base4;

    float eX = 0.f, eY = 0.f, eZ = 0.f, eW = 0.f;        // sum exp
    float swX = 0.f, swY = 0.f, swZ = 0.f, swW = 0.f;    // sum s*w
    float slX = 0.f, slY = 0.f, slZ = 0.f, slW = 0.f;    // sum s*w*l

    #pragma unroll
    for (int c = 0; c < CC; c++) {
        float4 l = __ldcs(&Lp[c * HW4]);
        float4 s = __ldcs(&Sp[c * HW4]);
        float wc = s_w[c];
        eX += __expf(l.x); eY += __expf(l.y); eZ += __expf(l.z); eW += __expf(l.w);
        float a = s.x * wc, bb2 = s.y * wc, cc2 = s.z * wc, dd = s.w * wc;
        swX += a;        swY += bb2;       swZ += cc2;       swW += dd;
        slX += a * l.x;  slY += bb2 * l.y; slZ += cc2 * l.z; slW += dd * l.w;
    }

    float4 loss;
    loss.x = swX * __logf(eX) - slX;
    loss.y = swY * __logf(eY) - slY;
    loss.z = swZ * __logf(eZ) - slZ;
    loss.w = swW * __logf(eW) - slW;
    g_loss4[tid] = loss;

    atomicAdd(&s_h[__float_as_uint(loss.x) >> 20], 1u);
    atomicAdd(&s_h[__float_as_uint(loss.y) >> 20], 1u);
    atomicAdd(&s_h[__float_as_uint(loss.z) >> 20], 1u);
    atomicAdd(&s_h[__float_as_uint(loss.w) >> 20], 1u);

    __syncthreads();
    for (int i = t; i < NBINS; i += 256) {
        unsigned c = s_h[i];
        if (c) atomicAdd(&g_hist1[i], c);
    }
}

// ---------------------------------------------------------------------------
// K2: fused select0 + fine pass.
// Every block recomputes bstar from g_hist1 (L2-broadcast, ~16KB), then
// streams its 16 elements/thread: sum values in bins > bstar (float regs),
// count fine bins inside bstar (counts only, midpoint reconstruction later).
// ---------------------------------------------------------------------------
__global__ void __launch_bounds__(256) fine_kernel() {
    __shared__ unsigned s_h[NBINS];
    __shared__ unsigned s_wsum[8];
    __shared__ int      s_bstar;
    __shared__ double   s_red[8];

    int t = threadIdx.x;
    int lane = t & 31, wid = t >> 5;

    for (int i = t; i < NBINS; i += 256) s_h[i] = 0u;

    // ---- per-block bstar from coarse histogram (identical in all blocks) ----
    unsigned c[16];
    unsigned run = 0;
    #pragma unroll
    for (int j = 0; j < 16; j++) {
        run += __ldg(&g_hist1[4095 - (16 * t + j)]);
        c[j] = run;
    }
    unsigned x = run;                       // warp inclusive scan of totals
    #pragma unroll
    for (int o = 1; o < 32; o <<= 1) {
        unsigned y = __shfl_up_sync(0xffffffffu, x, o);
        if (lane >= o) x += y;
    }
    if (lane == 31) s_wsum[wid] = x;
    __syncthreads();
    unsigned base = 0;
    #pragma unroll
    for (int w = 0; w < 8; w++) base += (w < wid) ? s_wsum[w] : 0u;
    unsigned ex = base + (x - run);         // exclusive prefix for this thread
    #pragma unroll
    for (int j = 0; j < 16; j++) {
        unsigned cum  = ex + c[j];
        unsigned prev = j ? (ex + c[j - 1]) : ex;
        if (cum >= TOPK && prev < TOPK) s_bstar = 4095 - (16 * t + j);
    }
    __syncthreads();                        // also covers s_h zero completion
    unsigned bstar = (unsigned)s_bstar;

    // ---- streaming pass: 4 independent float4 loads per thread (MLP=4) ----
    int g = blockIdx.x * 256 + t;           // 0..131071
    float4 a0 = g_loss4[g];
    float4 a1 = g_loss4[g + 131072];
    float4 a2 = g_loss4[g + 262144];
    float4 a3 = g_loss4[g + 393216];

    float acc0 = 0.f, acc1 = 0.f, acc2 = 0.f, acc3 = 0.f;
    #define PROC(v, acc) { unsigned bb_ = __float_as_uint(v); unsigned cb_ = bb_ >> 20; \
        if (cb_ > bstar) acc += (v); \
        else if (cb_ == bstar) atomicAdd(&s_h[(bb_ >> 8) & 0xFFFu], 1u); }
    PROC(a0.x, acc0) PROC(a0.y, acc1) PROC(a0.z, acc2) PROC(a0.w, acc3)
    PROC(a1.x, acc0) PROC(a1.y, acc1) PROC(a1.z, acc2) PROC(a1.w, acc3)
    PROC(a2.x, acc0) PROC(a2.y, acc1) PROC(a2.z, acc2) PROC(a2.w, acc3)
    PROC(a3.x, acc0) PROC(a3.y, acc1) PROC(a3.z, acc2) PROC(a3.w, acc3)
    #undef PROC

    // block-reduce sum_gt (promote to double only here)
    double gt = (double)acc0 + (double)acc1 + (double)acc2 + (double)acc3;
    #pragma unroll
    for (int o = 16; o; o >>= 1) gt += __shfl_down_sync(0xffffffffu, gt, o);
    if (lane == 0) s_red[wid] = gt;
    __syncthreads();
    if (t == 0) {
        double s = 0.0;
        #pragma unroll
        for (int i = 0; i < 8; i++) s += s_red[i];
        atomicAdd(&g_sum_gt, s);
    }
    // merge fine counts (only nonzero bins)
    for (int i = t; i < NBINS; i += 256) {
        unsigned cc2 = s_h[i];
        if (cc2) atomicAdd(&g_hist2[i], cc2);
    }
}

// ---------------------------------------------------------------------------
// block-wide top-down crossing search over a 4096-bin histogram (1024 thr).
// ---------------------------------------------------------------------------
__device__ void scan_find(const unsigned* __restrict__ hist, unsigned K,
                          int* out_bin, unsigned* out_need) {
    __shared__ unsigned sw[32];
    __shared__ int      sr;
    __shared__ unsigned sn;
    int t = threadIdx.x, lane = t & 31, wid = t >> 5;

    unsigned c[4];
    unsigned run = 0;
    #pragma unroll
    for (int j = 0; j < 4; j++) { run += hist[4095 - (4 * t + j)]; c[j] = run; }
    unsigned x = run;
    #pragma unroll
    for (int o = 1; o < 32; o <<= 1) {
        unsigned y = __shfl_up_sync(0xffffffffu, x, o);
        if (lane >= o) x += y;
    }
    if (lane == 31) sw[wid] = x;
    __syncthreads();
    unsigned base = 0;
    #pragma unroll
    for (int w = 0; w < 32; w++) base += (w < wid) ? sw[w] : 0u;
    unsigned ex = base + (x - run);
    #pragma unroll
    for (int j = 0; j < 4; j++) {
        unsigned cum  = ex + c[j];
        unsigned prev = j ? (ex + c[j - 1]) : ex;
        if (cum >= K && prev < K) { sr = 4095 - (4 * t + j); sn = K - prev; }
    }
    __syncthreads();
    *out_bin = sr;
    *out_need = sn;
    __syncthreads();   // allow shared reuse on next call
}

// ---------------------------------------------------------------------------
// K3: finalize. Recompute bstar/need from hist1, find fine threshold in
// hist2, reconstruct sums from fine-bin midpoints, write result, and
// self-clean all scratch for the next graph replay.
// ---------------------------------------------------------------------------
__global__ void __launch_bounds__(1024) final_kernel(float* out) {
    __shared__ double s_red[32];
    int t = threadIdx.x, lane = t & 31, wid = t >> 5;

    int bstar; unsigned need;
    scan_find(g_hist1, TOPK, &bstar, &need);

    int fstar; unsigned need2;
    scan_find(g_hist2, need, &fstar, &need2);

    // sum of cnt * midpoint for fine bins strictly above fstar
    double acc = 0.0;
    #pragma unroll
    for (int j = 0; j < 4; j++) {
        int fb = 4 * t + j;
        if (fb > fstar) {
            unsigned cnt = g_hist2[fb];
            if (cnt) {
                float mid = __uint_as_float(((unsigned)bstar << 20) | ((unsigned)fb << 8) | 0x80u);
                acc += (double)cnt * (double)mid;
            }
        }
    }
    #pragma unroll
    for (int o = 16; o; o >>= 1) acc += __shfl_down_sync(0xffffffffu, acc, o);
    if (lane == 0) s_red[wid] = acc;
    __syncthreads();
    if (t == 0) {
        double fine_above = 0.0;
        #pragma unroll
        for (int i = 0; i < 32; i++) fine_above += s_red[i];
        float midt = __uint_as_float(((unsigned)bstar << 20) | ((unsigned)fstar << 8) | 0x80u);
        double total = g_sum_gt + fine_above + (double)need2 * (double)midt;
        out[0] = (float)(total / (double)TOPK);
    }
    __syncthreads();

    // self-clean scratch for next replay
    for (int i = t; i < NBINS; i += 1024) { g_hist1[i] = 0u; g_hist2[i] = 0u; }
    if (t == 0) g_sum_gt = 0.0;
}

// ---------------------------------------------------------------------------
extern "C" void kernel_launch(void* const* d_in, const int* in_sizes, int n_in,
                              void* d_out, int out_size) {
    const float4* logits = (const float4*)d_in[0];
    // d_in[1] = labels (int64) — unused by the reference computation
    const float4* smooth = (const float4*)d_in[2];
    const float*  w2     = (const float*)d_in[3];
    float* out = (float*)d_out;

    loss_kernel<<<NPIX4 / 256, 256>>>(logits, smooth, w2);
    fine_kernel<<<FG, 256>>>();
    final_kernel<<<1, 1024>>>(out);
}